// round 4
// baseline (speedup 1.0000x reference)
#include <cuda_runtime.h>
#include <math.h>

#define NPOS 512
#define NALL 1024
#define DIM  512
#define EPSV 1e-5f
#define COSEPS 1e-8f
#define TILE 64
#define DK   32          // floats per chunk (16 k-pairs)
#define NKP  16          // k-pairs per chunk
#define SROW 66          // float2 per smem row (64 data + 2 pad)
#define NTHR 512

// ---------------- device scratch ----------------
__device__ float g_rnorm[NALL];
__device__ float g_t1[NPOS];
__device__ float g_t2[NALL];
__device__ float g_deno[NPOS];
__device__ float g_total;
__device__ unsigned g_negdone;
__device__ unsigned g_alldone;

__device__ __forceinline__ float warp_sum(float v) {
#pragma unroll
    for (int o = 16; o; o >>= 1) v += __shfl_xor_sync(0xffffffffu, v, o);
    return v;
}

typedef unsigned long long ull;

// packed fp32x2 ops
__device__ __forceinline__ ull ff2(ull a, ull b, ull c) {
    ull d;
    asm("fma.rn.f32x2 %0, %1, %2, %3;" : "=l"(d) : "l"(a), "l"(b), "l"(c));
    return d;
}
__device__ __forceinline__ ull fadd2(ull a, ull b) {
    ull d;
    asm("add.rn.f32x2 %0, %1, %2;" : "=l"(d) : "l"(a), "l"(b));
    return d;
}
__device__ __forceinline__ float lo2(ull v) { return __uint_as_float((unsigned)v); }
__device__ __forceinline__ float hi2(ull v) { return __uint_as_float((unsigned)(v >> 32)); }

__device__ __forceinline__ float sp(float x) {   // softplus, stable
    return fmaxf(x, 0.f) + log1pf(expf(-fabsf(x)));
}

// ---------------- kernel 1: per-row norm, t1, t2 (+ scratch init) ----------------
__global__ void row_kernel(const float* __restrict__ pos,
                           const float* __restrict__ neg,
                           const float* __restrict__ w) {
    int row = blockIdx.x;                       // 0..1023
    int t = threadIdx.x;                        // 128
    if (t == 0) {
        if (row < NPOS) g_deno[row] = 0.f;
        if (row == 0) { g_total = 0.f; g_negdone = 0u; g_alldone = 0u; }
    }
    const float* src = (row < NPOS) ? (pos + row * DIM) : (neg + (row - NPOS) * DIM);
    float4 v  = ((const float4*)src)[t];
    float4 u1 = ((const float4*)w)[t];
    float4 u2 = ((const float4*)(w + DIM))[t];
    float ss = v.x * v.x; ss = fmaf(v.y, v.y, ss); ss = fmaf(v.z, v.z, ss); ss = fmaf(v.w, v.w, ss);
    float d1 = v.x * u1.x; d1 = fmaf(v.y, u1.y, d1); d1 = fmaf(v.z, u1.z, d1); d1 = fmaf(v.w, u1.w, d1);
    float d2 = v.x * u2.x; d2 = fmaf(v.y, u2.y, d2); d2 = fmaf(v.z, u2.z, d2); d2 = fmaf(v.w, u2.w, d2);
    ss = warp_sum(ss); d1 = warp_sum(d1); d2 = warp_sum(d2);
    __shared__ float red[3][4];
    int wid = t >> 5, lid = t & 31;
    if (lid == 0) { red[0][wid] = ss; red[1][wid] = d1; red[2][wid] = d2; }
    __syncthreads();
    if (t == 0) {
        float S  = red[0][0] + red[0][1] + red[0][2] + red[0][3];
        float D1 = red[1][0] + red[1][1] + red[1][2] + red[1][3];
        float D2 = red[2][0] + red[2][1] + red[2][2] + red[2][3];
        g_rnorm[row] = 1.f / fmaxf(sqrtf(S), COSEPS);
        g_t2[row] = D2;
        if (row < NPOS) g_t1[row] = D1;
    }
}

// ---------------- kernel 2: fused pair kernel ----------------
// grid (16, 8): bx<8 -> pos-vs-pos (loss1 + bce), bx>=8 -> pos-vs-neg (deno + bce)
// 512 threads, per-thread 2n x 4m packed pairs (8 accumulator pairs)
__global__ void __launch_bounds__(NTHR, 1) pair_kernel(
    const float* __restrict__ pos, const float* __restrict__ neg,
    const float* __restrict__ w, const float* __restrict__ bptr,
    float* __restrict__ out)
{
    __shared__ __align__(16) float2 sA[NKP][SROW];  // [k-pair][row]
    __shared__ __align__(16) float2 sB[NKP][SROW];
    __shared__ float2 sW2[NKP];
    __shared__ float sRed[16];

    const int t  = threadIdx.x;
    const int tx = t & 15;       // m: 4 cols each
    const int ty = t >> 4;       // n: 2 rows each (0..31)
    const int n0 = blockIdx.y * TILE;
    const int m0 = blockIdx.x * TILE;
    const bool pos_half = (m0 < NPOS);
    const float* Bsrc = pos_half ? pos : neg;
    const int mrow0 = pos_half ? m0 : (m0 - NPOS);
    const float* w3 = w + 2 * DIM;

    const ull ABSM = 0x7FFFFFFF7FFFFFFFULL;
    const ull SGN2 = 0x8000000080000000ULL;

    ull dot2[2][4], t32[2][4];
#pragma unroll
    for (int i = 0; i < 2; i++)
#pragma unroll
        for (int j = 0; j < 4; j++) { dot2[i][j] = 0ULL; t32[i][j] = 0ULL; }

    // loader layout: thread -> (kp = t&15, rows 2*(t>>4), 2*(t>>4)+1)
    const int kp = t & 15;
    const int lr = (t >> 4) * 2;

    float2 pfA[2], pfB[2], pfW;
#define LOADC(D0) do {                                                         \
    pfA[0] = *(const float2*)(pos  + (n0 + lr)     * DIM + (D0) + 2 * kp);     \
    pfA[1] = *(const float2*)(pos  + (n0 + lr + 1) * DIM + (D0) + 2 * kp);     \
    pfB[0] = *(const float2*)(Bsrc + (mrow0 + lr)     * DIM + (D0) + 2 * kp);  \
    pfB[1] = *(const float2*)(Bsrc + (mrow0 + lr + 1) * DIM + (D0) + 2 * kp);  \
    if (t < NKP) pfW = *(const float2*)(w3 + (D0) + 2 * t);                    \
} while (0)

    LOADC(0);
    for (int c = 0; c < DIM / DK; c++) {
        __syncthreads();
        sA[kp][lr]     = pfA[0];
        sA[kp][lr + 1] = pfA[1];
        sB[kp][lr]     = pfB[0];
        sB[kp][lr + 1] = pfB[1];
        if (t < NKP) sW2[t] = pfW;
        __syncthreads();
        if (c < DIM / DK - 1) LOADC((c + 1) * DK);

#pragma unroll
        for (int kk = 0; kk < NKP; kk++) {
            ulonglong2 Av = *(const ulonglong2*)&sA[kk][ty * 2];
            ulonglong2 B0 = *(const ulonglong2*)&sB[kk][tx * 4];
            ulonglong2 B1 = *(const ulonglong2*)&sB[kk][tx * 4 + 2];
            ull a2[2] = {Av.x, Av.y};
            ull b2[4] = {B0.x, B0.y, B1.x, B1.y};
            ull w2 = *(const ull*)&sW2[kk];
            ull nb[4];
#pragma unroll
            for (int j = 0; j < 4; j++) nb[j] = b2[j] ^ SGN2;
#pragma unroll
            for (int i = 0; i < 2; i++) {
#pragma unroll
                for (int j = 0; j < 4; j++) {
                    dot2[i][j] = ff2(a2[i], b2[j], dot2[i][j]);
                    ull d = fadd2(a2[i], nb[j]) & ABSM;   // |a-b| packed
                    t32[i][j] = ff2(d, w2, t32[i][j]);
                }
            }
        }
    }

    // ---- epilogue ----
    int gn[2];
    float rn_n[2], t1v[2], rn_m[4], t2v[4];
#pragma unroll
    for (int i = 0; i < 2; i++) {
        gn[i] = n0 + ty * 2 + i;
        rn_n[i] = g_rnorm[gn[i]];
        t1v[i]  = g_t1[gn[i]];
    }
#pragma unroll
    for (int j = 0; j < 4; j++) {
        int gm = m0 + tx * 4 + j;
        rn_m[j] = g_rnorm[gm];
        t2v[j]  = g_t2[gm];
    }
    float bias = __ldg(bptr);

    float part = 0.f;

    if (!pos_half) {
        // ---- negative half: bce + deno ----
        float bce = 0.f, dl[2] = {0.f, 0.f};
#pragma unroll
        for (int i = 0; i < 2; i++) {
#pragma unroll
            for (int j = 0; j < 4; j++) {
                float dot = lo2(dot2[i][j]) + hi2(dot2[i][j]);
                float t3  = lo2(t32[i][j])  + hi2(t32[i][j]);
                float cc = dot * rn_n[i] * rn_m[j];
                float logit = t1v[i] + t2v[j] + t3 + bias;
                bce += sp(logit);              // label 0
                dl[i] += expf(cc);
            }
        }
#pragma unroll
        for (int i = 0; i < 2; i++) {
            float v = dl[i];
            v += __shfl_xor_sync(0xffffffffu, v, 1);
            v += __shfl_xor_sync(0xffffffffu, v, 2);
            v += __shfl_xor_sync(0xffffffffu, v, 4);
            v += __shfl_xor_sync(0xffffffffu, v, 8);
            if (tx == 0) atomicAdd(&g_deno[gn[i]], v);
        }
        __threadfence();                       // publish deno before negdone arrive
        part = bce * (1.0f / (float)NALL);
    } else {
        // ---- positive half: wait for deno, then bce + contrastive ----
        if (t == 0) {
            while (atomicCAS(&g_negdone, 64u, 64u) != 64u) { __nanosleep(200); }
        }
        __syncthreads();
        __threadfence();
        float dn[2];
#pragma unroll
        for (int i = 0; i < 2; i++) dn[i] = __ldcg(&g_deno[gn[i]]);

        float bce = 0.f, l1 = 0.f;
#pragma unroll
        for (int i = 0; i < 2; i++) {
#pragma unroll
            for (int j = 0; j < 4; j++) {
                float dot = lo2(dot2[i][j]) + hi2(dot2[i][j]);
                float t3  = lo2(t32[i][j])  + hi2(t32[i][j]);
                float cc = dot * rn_n[i] * rn_m[j];
                float logit = t1v[i] + t2v[j] + t3 + bias;
                bce += sp(-logit);             // label 1
                l1 += logf(dn[i] + expf(cc) + EPSV) - cc;
            }
        }
        part = bce * (1.0f / (float)NALL) + l1;
    }

    // ---- block reduce + global accumulate + completion protocol ----
    float v = warp_sum(part);
    if ((t & 31) == 0) sRed[t >> 5] = v;
    __syncthreads();
    if (t == 0) {
        float s = 0.f;
#pragma unroll
        for (int k = 0; k < 16; k++) s += sRed[k];
        atomicAdd(&g_total, s);
        __threadfence();
        if (!pos_half) atomicAdd(&g_negdone, 1u);
        unsigned old = atomicAdd(&g_alldone, 1u);
        if (old == 127u) {
            __threadfence();
            out[0] = atomicAdd(&g_total, 0.f);
        }
    }
}

// ---------------- launch ----------------
extern "C" void kernel_launch(void* const* d_in, const int* in_sizes, int n_in,
                              void* d_out, int out_size) {
    const float* pos = (const float*)d_in[0];   // [512,512]
    const float* neg = (const float*)d_in[1];   // [512,512]
    const float* w   = (const float*)d_in[2];   // [1,1536]
    const float* b   = (const float*)d_in[3];   // [1]
    float* out = (float*)d_out;

    row_kernel<<<NALL, 128>>>(pos, neg, w);
    dim3 grid(NALL / TILE, NPOS / TILE);        // (16, 8) — one wave, 128 blocks
    pair_kernel<<<grid, NTHR>>>(pos, neg, w, b, out);
}

// round 5
// speedup vs baseline: 1.2024x; 1.2024x over previous
#include <cuda_runtime.h>
#include <math.h>

#define NPOS 512
#define NALL 1024
#define DIM  512
#define EPSV 1e-5f
#define COSEPS 1e-8f
#define TILE 64
#define DK   32
#define SPAD 68   // padded smem row (floats)

// ---------------- device scratch ----------------
__device__ float g_rnorm[NALL];
__device__ float g_t1[NPOS];
__device__ float g_t2[NALL];
__device__ float g_deno[NPOS];
__device__ float g_total;
__device__ unsigned g_negdone;
__device__ unsigned g_alldone;

__device__ __forceinline__ float warp_sum(float v) {
#pragma unroll
    for (int o = 16; o; o >>= 1) v += __shfl_xor_sync(0xffffffffu, v, o);
    return v;
}

__device__ __forceinline__ float sp(float x) {   // softplus, stable
    return fmaxf(x, 0.f) + log1pf(expf(-fabsf(x)));
}

// ---------------- kernel 1: per-row norm, t1, t2 (+ scratch init) ----------------
__global__ void row_kernel(const float* __restrict__ pos,
                           const float* __restrict__ neg,
                           const float* __restrict__ w) {
    int row = blockIdx.x;                       // 0..1023
    int t = threadIdx.x;                        // 128
    if (t == 0) {
        if (row < NPOS) g_deno[row] = 0.f;
        if (row == 0) { g_total = 0.f; g_negdone = 0u; g_alldone = 0u; }
    }
    const float* src = (row < NPOS) ? (pos + row * DIM) : (neg + (row - NPOS) * DIM);
    float4 v  = ((const float4*)src)[t];
    float4 u1 = ((const float4*)w)[t];
    float4 u2 = ((const float4*)(w + DIM))[t];
    float ss = v.x * v.x; ss = fmaf(v.y, v.y, ss); ss = fmaf(v.z, v.z, ss); ss = fmaf(v.w, v.w, ss);
    float d1 = v.x * u1.x; d1 = fmaf(v.y, u1.y, d1); d1 = fmaf(v.z, u1.z, d1); d1 = fmaf(v.w, u1.w, d1);
    float d2 = v.x * u2.x; d2 = fmaf(v.y, u2.y, d2); d2 = fmaf(v.z, u2.z, d2); d2 = fmaf(v.w, u2.w, d2);
    ss = warp_sum(ss); d1 = warp_sum(d1); d2 = warp_sum(d2);
    __shared__ float red[3][4];
    int wid = t >> 5, lid = t & 31;
    if (lid == 0) { red[0][wid] = ss; red[1][wid] = d1; red[2][wid] = d2; }
    __syncthreads();
    if (t == 0) {
        float S  = red[0][0] + red[0][1] + red[0][2] + red[0][3];
        float D1 = red[1][0] + red[1][1] + red[1][2] + red[1][3];
        float D2 = red[2][0] + red[2][1] + red[2][2] + red[2][3];
        g_rnorm[row] = 1.f / fmaxf(sqrtf(S), COSEPS);
        g_t2[row] = D2;
        if (row < NPOS) g_t1[row] = D1;
    }
}

// ---------------- kernel 2: fused pair kernel (scalar 4x4 mainloop) ----------------
// grid (16, 8): bx<8 -> pos-vs-pos (loss1 + bce), bx>=8 -> pos-vs-neg (deno + bce)
__global__ void __launch_bounds__(256, 1) pair_kernel(
    const float* __restrict__ pos, const float* __restrict__ neg,
    const float* __restrict__ w, const float* __restrict__ bptr,
    float* __restrict__ out)
{
    __shared__ float sA[DK][SPAD];   // [d][row], transposed tiles
    __shared__ float sB[DK][SPAD];
    __shared__ float sW[DK];
    __shared__ float sRed[8];

    const int t  = threadIdx.x;
    const int tx = t & 15, ty = t >> 4;
    const int n0 = blockIdx.y * TILE;
    const int m0 = blockIdx.x * TILE;
    const bool pos_half = (m0 < NPOS);
    const float* Bsrc = pos_half ? pos : neg;
    const int mrow0 = pos_half ? m0 : (m0 - NPOS);
    const float* w3 = w + 2 * DIM;

    float dotv[4][4], t3v[4][4];
#pragma unroll
    for (int i = 0; i < 4; i++)
#pragma unroll
        for (int j = 0; j < 4; j++) { dotv[i][j] = 0.f; t3v[i][j] = 0.f; }

    const int lc = t & 31;   // d within chunk (coalesced global reads)
    const int lr = t >> 5;   // row group

    for (int d0 = 0; d0 < DIM; d0 += DK) {
        if (t < DK) sW[t] = w3[d0 + t];
#pragma unroll
        for (int rr = 0; rr < TILE; rr += 8) {
            int r = rr + lr;
            sA[lc][r] = pos [(n0 + r)    * DIM + d0 + lc];
            sB[lc][r] = Bsrc[(mrow0 + r) * DIM + d0 + lc];
        }
        __syncthreads();
#pragma unroll 8
        for (int kk = 0; kk < DK; kk++) {
            float4 av = *(const float4*)&sA[kk][ty * 4];
            float4 bv = *(const float4*)&sB[kk][tx * 4];
            float a[4] = {av.x, av.y, av.z, av.w};
            float b[4] = {bv.x, bv.y, bv.z, bv.w};
            float wv = sW[kk];
#pragma unroll
            for (int i = 0; i < 4; i++)
#pragma unroll
                for (int j = 0; j < 4; j++) {
                    dotv[i][j] = fmaf(a[i], b[j], dotv[i][j]);
                    t3v[i][j]  = fmaf(fabsf(a[i] - b[j]), wv, t3v[i][j]);
                }
        }
        __syncthreads();
    }

    // ---- epilogue ----
    int gn[4];
    float rn_n[4], t1v[4], rn_m[4], t2v[4];
#pragma unroll
    for (int i = 0; i < 4; i++) {
        gn[i] = n0 + ty * 4 + i;
        rn_n[i] = g_rnorm[gn[i]];
        t1v[i]  = g_t1[gn[i]];
    }
#pragma unroll
    for (int j = 0; j < 4; j++) {
        int gm = m0 + tx * 4 + j;
        rn_m[j] = g_rnorm[gm];
        t2v[j]  = g_t2[gm];
    }
    float bias = __ldg(bptr);

    float part = 0.f;

    if (!pos_half) {
        // ---- negative half: bce(label 0) + deno ----
        float bce = 0.f, dl[4] = {0.f, 0.f, 0.f, 0.f};
#pragma unroll
        for (int i = 0; i < 4; i++) {
#pragma unroll
            for (int j = 0; j < 4; j++) {
                float cc = dotv[i][j] * rn_n[i] * rn_m[j];
                float logit = t1v[i] + t2v[j] + t3v[i][j] + bias;
                bce += sp(logit);
                dl[i] += expf(cc);
            }
        }
#pragma unroll
        for (int i = 0; i < 4; i++) {
            float v = dl[i];
            v += __shfl_xor_sync(0xffffffffu, v, 1);
            v += __shfl_xor_sync(0xffffffffu, v, 2);
            v += __shfl_xor_sync(0xffffffffu, v, 4);
            v += __shfl_xor_sync(0xffffffffu, v, 8);
            if (tx == 0) atomicAdd(&g_deno[gn[i]], v);
        }
        __threadfence();                       // publish deno before negdone arrive
        part = bce * (1.0f / (float)NALL);
    } else {
        // ---- positive half: wait for deno, then bce(label 1) + contrastive ----
        if (t == 0) {
            while (atomicCAS(&g_negdone, 64u, 64u) != 64u) { __nanosleep(200); }
        }
        __syncthreads();
        __threadfence();
        float dn[4];
#pragma unroll
        for (int i = 0; i < 4; i++) dn[i] = __ldcg(&g_deno[gn[i]]);

        float bce = 0.f, l1 = 0.f;
#pragma unroll
        for (int i = 0; i < 4; i++) {
#pragma unroll
            for (int j = 0; j < 4; j++) {
                float cc = dotv[i][j] * rn_n[i] * rn_m[j];
                float logit = t1v[i] + t2v[j] + t3v[i][j] + bias;
                bce += sp(-logit);
                l1 += logf(dn[i] + expf(cc) + EPSV) - cc;  // -log(e^c/(deno+e^c+eps))
            }
        }
        part = bce * (1.0f / (float)NALL) + l1;
    }

    // ---- block reduce + global accumulate + completion protocol ----
    float v = warp_sum(part);
    if ((t & 31) == 0) sRed[t >> 5] = v;
    __syncthreads();
    if (t == 0) {
        float s = 0.f;
#pragma unroll
        for (int k = 0; k < 8; k++) s += sRed[k];
        atomicAdd(&g_total, s);
        __threadfence();
        if (!pos_half) atomicAdd(&g_negdone, 1u);
        unsigned old = atomicAdd(&g_alldone, 1u);
        if (old == 127u) {
            __threadfence();
            out[0] = atomicAdd(&g_total, 0.f);
        }
    }
}

// ---------------- launch ----------------
extern "C" void kernel_launch(void* const* d_in, const int* in_sizes, int n_in,
                              void* d_out, int out_size) {
    const float* pos = (const float*)d_in[0];   // [512,512]
    const float* neg = (const float*)d_in[1];   // [512,512]
    const float* w   = (const float*)d_in[2];   // [1,1536]
    const float* b   = (const float*)d_in[3];   // [1]
    float* out = (float*)d_out;

    row_kernel<<<NALL, 128>>>(pos, neg, w);
    dim3 grid(NALL / TILE, NPOS / TILE);        // (16, 8) — one wave, 128 blocks
    pair_kernel<<<grid, 256>>>(pos, neg, w, b, out);
}